// round 14
// baseline (speedup 1.0000x reference)
#include <cuda_runtime.h>
#include <cstdint>

#define NN 50000
#define KD 512
#define EM 128
#define OD 64
#define EE 1600000
#define SCAN_B 196            // 196 * 256 = 50176 >= NN

// ---------------- scratch (device globals) ----------------
__device__ float g_g[(size_t)NN * OD];
__device__ float g_as[NN];
__device__ float g_ad[NN];
__device__ int   g_cnt[NN];
__device__ int   g_off[NN];
__device__ int   g_pos[NN];
__device__ int   g_esrc[EE];
__device__ int   g_bsum[SCAN_B];
__device__ int   g_boff[SCAN_B];

__device__ __forceinline__ float to_tf32(float x) {
    float r;
    asm("cvt.rna.tf32.f32 %0, %1;" : "=f"(r) : "f"(x));
    return r;
}

// ---------------- CSR build (parallel, coalesced) ----------------
__global__ void k_hist(const int* __restrict__ ei, int E) {
    int i = blockIdx.x * blockDim.x + threadIdx.x;
    if (i < E) atomicAdd(g_cnt + ei[E + i], 1);
}

__global__ __launch_bounds__(256) void k_scan1() {
    __shared__ int sh[256];
    int t = threadIdx.x;
    int i = blockIdx.x * 256 + t;
    int v = (i < NN) ? g_cnt[i] : 0;
    sh[t] = v;
    __syncthreads();
#pragma unroll
    for (int o = 128; o > 0; o >>= 1) {
        if (t < o) sh[t] += sh[t + o];
        __syncthreads();
    }
    if (t == 0) g_bsum[blockIdx.x] = sh[0];
}

__global__ __launch_bounds__(256) void k_scan2() {
    __shared__ int sh[256];
    int t = threadIdx.x;
    int v = (t < SCAN_B) ? g_bsum[t] : 0;
    sh[t] = v;
    __syncthreads();
#pragma unroll
    for (int o = 1; o < 256; o <<= 1) {
        int u = (t >= o) ? sh[t - o] : 0;
        __syncthreads();
        sh[t] += u;
        __syncthreads();
    }
    if (t < SCAN_B) g_boff[t] = sh[t] - v;
}

__global__ __launch_bounds__(256) void k_scan3() {
    __shared__ int sh[256];
    int t = threadIdx.x;
    int i = blockIdx.x * 256 + t;
    int v = (i < NN) ? g_cnt[i] : 0;
    sh[t] = v;
    __syncthreads();
#pragma unroll
    for (int o = 1; o < 256; o <<= 1) {
        int u = (t >= o) ? sh[t - o] : 0;
        __syncthreads();
        sh[t] += u;
        __syncthreads();
    }
    if (i < NN) {
        int off = g_boff[blockIdx.x] + sh[t] - v;
        g_off[i] = off;
        g_pos[i] = off;
    }
}

__global__ void k_scatter(const int* __restrict__ ei, int E) {
    int i = blockIdx.x * blockDim.x + threadIdx.x;
    if (i >= E) return;
    int s = ei[i];
    int d = ei[E + i];
    int p = atomicAdd(g_pos + d, 1);
    g_esrc[p] = s;
}

// ---------------- FUSED GEMM: h = lrelu(X@Wd^T+bd); g = h@Wg^T; logits ------
// Phase 1: tf32 mma + 2-stage cp.async (128x128 h tile, K=512).
// Phase 2: h tile stays in smem (overlays pipeline buffers), 128x64 mma K=128,
//          emits g + a_src/a_dst. g_h global round-trip eliminated.
#define G1_BM 128
#define G1_BK 32
#define G1_ROW 36
#define G1_TILE (G1_BM * G1_ROW)          // 4608 floats
#define PIPE_FLOATS (4 * G1_TILE)         // 18432 floats (2 stages A+B)
#define HS_ROW 132                        // h tile row stride (128 + 4 pad)
#define WGS_OFF PIPE_FLOATS               // Wgs: [64][HS_ROW]
#define PS_OFF  (WGS_OFF + OD * HS_ROW)   // ps_sh[128][2]
#define PD_OFF  (PS_OFF + 256)
#define ATS_OFF (PD_OFF + 256)
#define ATD_OFF (ATS_OFF + OD)
#define FG_SMEM ((ATD_OFF + OD) * 4)      // total bytes

__global__ __launch_bounds__(256) void k_fused_gemm(const float* __restrict__ X,
                                                    const float* __restrict__ Wd,
                                                    const float* __restrict__ bd,
                                                    const float* __restrict__ Wg,
                                                    const float* __restrict__ att_s,
                                                    const float* __restrict__ att_d) {
    extern __shared__ float smem[];
    float* As  = smem;                  // [2][128][36]
    float* Bs  = smem + 2 * G1_TILE;    // [2][128][36]
    float* hs  = smem;                  // overlay after phase 1: [128][HS_ROW]
    float* Wgs = smem + WGS_OFF;        // [64][HS_ROW]
    float* ps_sh = smem + PS_OFF;       // [128][2]
    float* pd_sh = smem + PD_OFF;
    float* ats = smem + ATS_OFF;
    float* atd = smem + ATD_OFF;

    const int tid  = threadIdx.x;
    const int warp = tid >> 5;
    const int lane = tid & 31;
    const int g    = lane >> 2;
    const int tig  = lane & 3;
    const int wm   = warp >> 2;          // phase-1: 2 (M)
    const int wn   = warp & 3;           //          4 (N)
    const int row0 = blockIdx.x * G1_BM;

    const uint32_t a_base = (uint32_t)__cvta_generic_to_shared(As);
    const uint32_t b_base = (uint32_t)__cvta_generic_to_shared(Bs);

    // load Wg (tf32-rounded) + att vectors while pipeline starts
#pragma unroll
    for (int i = 0; i < 8; i++) {
        int f = tid + i * 256;           // 0..2047 -> 64 rows x 32 float4
        int c = f >> 5;
        int kq = f & 31;
        float4 v = *reinterpret_cast<const float4*>(Wg + (size_t)c * EM + kq * 4);
        v.x = to_tf32(v.x); v.y = to_tf32(v.y);
        v.z = to_tf32(v.z); v.w = to_tf32(v.w);
        *reinterpret_cast<float4*>(&Wgs[c * HS_ROW + kq * 4]) = v;
    }
    if (tid < OD) { ats[tid] = att_s[tid]; atd[tid] = att_d[tid]; }

    float acc[4][4][4];
#pragma unroll
    for (int i = 0; i < 4; i++)
#pragma unroll
        for (int j = 0; j < 4; j++)
#pragma unroll
            for (int r = 0; r < 4; r++) acc[i][j][r] = 0.f;

    auto load_stage = [&](int st, int k0) {
#pragma unroll
        for (int i = 0; i < 4; i++) {
            int f  = tid + i * 256;
            int r  = f >> 3;
            int kq = f & 7;
            int rg = row0 + r;
            if (rg > NN - 1) rg = NN - 1;    // clamp (stores masked later)
            const float* src = X + (size_t)rg * KD + k0 + kq * 4;
            uint32_t dst = a_base + (uint32_t)((st * G1_TILE + r * G1_ROW + kq * 4) * 4);
            asm volatile("cp.async.cg.shared.global [%0], [%1], 16;"
                         :: "r"(dst), "l"(src));
        }
#pragma unroll
        for (int i = 0; i < 4; i++) {
            int f  = tid + i * 256;
            int c  = f >> 3;
            int kq = f & 7;
            const float* src = Wd + (size_t)c * KD + k0 + kq * 4;
            uint32_t dst = b_base + (uint32_t)((st * G1_TILE + c * G1_ROW + kq * 4) * 4);
            asm volatile("cp.async.cg.shared.global [%0], [%1], 16;"
                         :: "r"(dst), "l"(src));
        }
        asm volatile("cp.async.commit_group;");
    };

    const int NCH = KD / G1_BK;   // 16
    load_stage(0, 0);
    for (int kt = 0; kt < NCH; kt++) {
        int st = kt & 1;
        if (kt + 1 < NCH) {
            load_stage(st ^ 1, (kt + 1) * G1_BK);
            asm volatile("cp.async.wait_group 1;");
        } else {
            asm volatile("cp.async.wait_group 0;");
        }
        __syncthreads();

        const float* A0 = As + st * G1_TILE;
        const float* B0 = Bs + st * G1_TILE;
#pragma unroll
        for (int ks = 0; ks < 4; ks++) {
            const int kb = ks * 8;
            uint32_t af[4][4];
#pragma unroll
            for (int mt = 0; mt < 4; mt++) {
                int ra = wm * 64 + mt * 16 + g;
                af[mt][0] = __float_as_uint(to_tf32(A0[ra * G1_ROW + kb + tig]));
                af[mt][1] = __float_as_uint(to_tf32(A0[(ra + 8) * G1_ROW + kb + tig]));
                af[mt][2] = __float_as_uint(to_tf32(A0[ra * G1_ROW + kb + tig + 4]));
                af[mt][3] = __float_as_uint(to_tf32(A0[(ra + 8) * G1_ROW + kb + tig + 4]));
            }
            uint32_t bf[4][2];
#pragma unroll
            for (int nt = 0; nt < 4; nt++) {
                int nb = wn * 32 + nt * 8 + g;
                bf[nt][0] = __float_as_uint(to_tf32(B0[nb * G1_ROW + kb + tig]));
                bf[nt][1] = __float_as_uint(to_tf32(B0[nb * G1_ROW + kb + tig + 4]));
            }
#pragma unroll
            for (int mt = 0; mt < 4; mt++)
#pragma unroll
                for (int nt = 0; nt < 4; nt++) {
                    asm volatile(
                        "mma.sync.aligned.m16n8k8.row.col.f32.tf32.tf32.f32 "
                        "{%0,%1,%2,%3}, {%4,%5,%6,%7}, {%8,%9}, {%0,%1,%2,%3};"
                        : "+f"(acc[mt][nt][0]), "+f"(acc[mt][nt][1]),
                          "+f"(acc[mt][nt][2]), "+f"(acc[mt][nt][3])
                        : "r"(af[mt][0]), "r"(af[mt][1]), "r"(af[mt][2]), "r"(af[mt][3]),
                          "r"(bf[nt][0]), "r"(bf[nt][1]));
                }
        }
        __syncthreads();
    }

    // phase-1 epilogue: bias + lrelu + tf32-round, h tile -> smem (overlay)
#pragma unroll
    for (int mt = 0; mt < 4; mt++) {
#pragma unroll
        for (int half = 0; half < 2; half++) {
            int rloc = wm * 64 + mt * 16 + g + half * 8;
#pragma unroll
            for (int nt = 0; nt < 4; nt++) {
                int c = wn * 32 + nt * 8 + tig * 2;
                float v0 = acc[mt][nt][half * 2]     + __ldg(bd + c);
                float v1 = acc[mt][nt][half * 2 + 1] + __ldg(bd + c + 1);
                v0 = v0 > 0.f ? v0 : 0.01f * v0;
                v1 = v1 > 0.f ? v1 : 0.01f * v1;
                *reinterpret_cast<float2*>(&hs[rloc * HS_ROW + c]) =
                    make_float2(to_tf32(v0), to_tf32(v1));
            }
        }
    }
    __syncthreads();

    // ---- phase 2: g = h @ Wg^T (128x64, K=128), all operands in smem ----
    const int wm2 = warp >> 1;   // 0..3 -> rows wm2*32
    const int wn2 = warp & 1;    // 0..1 -> cols wn2*32

    float acc2[2][4][4];
#pragma unroll
    for (int i = 0; i < 2; i++)
#pragma unroll
        for (int j = 0; j < 4; j++)
#pragma unroll
            for (int r = 0; r < 4; r++) acc2[i][j][r] = 0.f;

#pragma unroll
    for (int ks = 0; ks < 16; ks++) {
        const int kb = ks * 8;
        uint32_t af[2][4];
#pragma unroll
        for (int mt = 0; mt < 2; mt++) {
            int ra = wm2 * 32 + mt * 16 + g;
            af[mt][0] = __float_as_uint(hs[ra * HS_ROW + kb + tig]);
            af[mt][1] = __float_as_uint(hs[(ra + 8) * HS_ROW + kb + tig]);
            af[mt][2] = __float_as_uint(hs[ra * HS_ROW + kb + tig + 4]);
            af[mt][3] = __float_as_uint(hs[(ra + 8) * HS_ROW + kb + tig + 4]);
        }
        uint32_t bf[4][2];
#pragma unroll
        for (int nt = 0; nt < 4; nt++) {
            int nb = wn2 * 32 + nt * 8 + g;
            bf[nt][0] = __float_as_uint(Wgs[nb * HS_ROW + kb + tig]);
            bf[nt][1] = __float_as_uint(Wgs[nb * HS_ROW + kb + tig + 4]);
        }
#pragma unroll
        for (int mt = 0; mt < 2; mt++)
#pragma unroll
            for (int nt = 0; nt < 4; nt++) {
                asm volatile(
                    "mma.sync.aligned.m16n8k8.row.col.f32.tf32.tf32.f32 "
                    "{%0,%1,%2,%3}, {%4,%5,%6,%7}, {%8,%9}, {%0,%1,%2,%3};"
                    : "+f"(acc2[mt][nt][0]), "+f"(acc2[mt][nt][1]),
                      "+f"(acc2[mt][nt][2]), "+f"(acc2[mt][nt][3])
                    : "r"(af[mt][0]), "r"(af[mt][1]), "r"(af[mt][2]), "r"(af[mt][3]),
                      "r"(bf[nt][0]), "r"(bf[nt][1]));
            }
    }

    // phase-2 epilogue: store g, per-row partial logits over this warp's 32 cols
#pragma unroll
    for (int mt = 0; mt < 2; mt++) {
#pragma unroll
        for (int half = 0; half < 2; half++) {
            int rloc = wm2 * 32 + mt * 16 + g + half * 8;
            int r = row0 + rloc;
            float ps = 0.f, pd = 0.f;
#pragma unroll
            for (int nt = 0; nt < 4; nt++) {
                int c = wn2 * 32 + nt * 8 + tig * 2;
                float v0 = acc2[mt][nt][half * 2];
                float v1 = acc2[mt][nt][half * 2 + 1];
                if (r < NN)
                    *reinterpret_cast<float2*>(g_g + (size_t)r * OD + c) = make_float2(v0, v1);
                ps = fmaf(v0, ats[c], fmaf(v1, ats[c + 1], ps));
                pd = fmaf(v0, atd[c], fmaf(v1, atd[c + 1], pd));
            }
            ps += __shfl_xor_sync(0xffffffffu, ps, 1);
            ps += __shfl_xor_sync(0xffffffffu, ps, 2);
            pd += __shfl_xor_sync(0xffffffffu, pd, 1);
            pd += __shfl_xor_sync(0xffffffffu, pd, 2);
            if (tig == 0) { ps_sh[rloc * 2 + wn2] = ps; pd_sh[rloc * 2 + wn2] = pd; }
        }
    }
    __syncthreads();
    if (tid < G1_BM) {
        int r = row0 + tid;
        if (r < NN) {
            g_as[r] = ps_sh[tid * 2] + ps_sh[tid * 2 + 1];
            g_ad[r] = pd_sh[tid * 2] + pd_sh[tid * 2 + 1];
        }
    }
}

// ---------------- fused softmax + gather accumulate (pipelined weight chain) --
__global__ __launch_bounds__(256) void k_accum(float* __restrict__ out,
                                               const float* __restrict__ bg) {
    const unsigned FULL = 0xffffffffu;
    int w    = (blockIdx.x * blockDim.x + threadIdx.x) >> 5;
    int lane = threadIdx.x & 31;
    if (w >= NN) return;
    int beg = g_off[w];
    int end = beg + g_cnt[w];
    float a_d = g_ad[w];

    // self loop
    float e0 = g_as[w] + a_d;
    e0 = e0 > 0.f ? e0 : 0.2f * e0;
    float wt_self = __expf(e0);
    float2 gw = *reinterpret_cast<const float2*>(g_g + (size_t)w * OD + lane * 2);
    float acc0 = wt_self * gw.x, acc1 = wt_self * gw.y;
    float den_l = (lane == 0) ? wt_self : 0.f;

    // prologue: chain for first batch
    int   s_l  = w;
    float wt_l = 0.f;
    if (beg < end && beg + lane < end) {
        s_l = g_esrc[beg + lane];
        float e = g_as[s_l] + a_d;
        e = e > 0.f ? e : 0.2f * e;
        wt_l = __expf(e);
    }

    for (int j = beg; j < end; j += 32) {
        int   jn   = j + 32;
        int   s_nl = w;
        float a_nl = 0.f;
        bool  nv   = false;
        if (jn < end && jn + lane < end) {
            s_nl = g_esrc[jn + lane];
            a_nl = g_as[s_nl];
            nv   = true;
        }

        den_l += wt_l;
#pragma unroll
        for (int hh = 0; hh < 2; hh++) {
            float2 gvs[16];
#pragma unroll
            for (int u = 0; u < 16; u++) {
                int s = __shfl_sync(FULL, s_l, hh * 16 + u);
                gvs[u] = *reinterpret_cast<const float2*>(g_g + (size_t)s * OD + lane * 2);
            }
#pragma unroll
            for (int u = 0; u < 16; u++) {
                float wt = __shfl_sync(FULL, wt_l, hh * 16 + u);
                acc0 = fmaf(wt, gvs[u].x, acc0);
                acc1 = fmaf(wt, gvs[u].y, acc1);
            }
        }

        float e = a_nl + a_d;
        e = e > 0.f ? e : 0.2f * e;
        wt_l = nv ? __expf(e) : 0.f;
        s_l  = s_nl;
    }
#pragma unroll
    for (int o = 16; o > 0; o >>= 1)
        den_l += __shfl_xor_sync(FULL, den_l, o);
    float inv = 1.f / den_l;
    int c = lane * 2;
    float2 b2 = *reinterpret_cast<const float2*>(bg + c);
    *reinterpret_cast<float2*>(out + (size_t)w * OD + c) =
        make_float2(acc0 * inv + b2.x, acc1 * inv + b2.y);
}

// ---------------- launch ----------------
extern "C" void kernel_launch(void* const* d_in, const int* in_sizes, int n_in,
                              void* d_out, int out_size) {
    const float* x   = (const float*)d_in[0];
    const int*   ei  = (const int*)  d_in[1];
    const float* Wd  = (const float*)d_in[2];
    const float* bd  = (const float*)d_in[3];
    const float* Wg  = (const float*)d_in[4];
    const float* ats = (const float*)d_in[5];
    const float* atd = (const float*)d_in[6];
    const float* bg  = (const float*)d_in[7];
    float* out = (float*)d_out;

    const int E = in_sizes[1] / 2;

    static cudaStream_t s2 = nullptr;
    static cudaEvent_t ev_fork = nullptr, ev_join = nullptr;
    static void* cnt_ptr = nullptr;
    if (!s2) {
        cudaStreamCreate(&s2);
        cudaEventCreateWithFlags(&ev_fork, cudaEventDisableTiming);
        cudaEventCreateWithFlags(&ev_join, cudaEventDisableTiming);
        cudaGetSymbolAddress(&cnt_ptr, g_cnt);
        cudaFuncSetAttribute(k_fused_gemm, cudaFuncAttributeMaxDynamicSharedMemorySize, FG_SMEM);
    }

    // fork: CSR build on s2 (memset is not a kernel launch)
    cudaEventRecord(ev_fork, 0);
    cudaStreamWaitEvent(s2, ev_fork, 0);

    cudaMemsetAsync(cnt_ptr, 0, NN * sizeof(int), s2);
    k_hist<<<(E + 255) / 256, 256, 0, s2>>>(ei, E);          // launch 1
    k_scan1<<<SCAN_B, 256, 0, s2>>>();                       // launch 2
    k_scan2<<<1, 256, 0, s2>>>();                            // launch 3

    k_fused_gemm<<<(NN + G1_BM - 1) / G1_BM, 256, FG_SMEM>>>(x, Wd, bd, Wg, ats, atd);  // launch 4 (profiled)

    k_scan3<<<SCAN_B, 256, 0, s2>>>();                       // launch 5
    k_scatter<<<(E + 255) / 256, 256, 0, s2>>>(ei, E);       // launch 6
    cudaEventRecord(ev_join, s2);

    cudaStreamWaitEvent(0, ev_join, 0);
    k_accum<<<(NN * 32 + 255) / 256, 256>>>(out, bg);
}

// round 15
// speedup vs baseline: 1.0434x; 1.0434x over previous
#include <cuda_runtime.h>
#include <cstdint>

#define NN 50000
#define KD 512
#define EM 128
#define OD 64
#define EE 1600000
#define SCAN_B 196            // 196 * 256 = 50176 >= NN

// ---------------- scratch (device globals) ----------------
__device__ float g_g[(size_t)NN * OD];
__device__ float g_as[NN];
__device__ float g_ad[NN];
__device__ int   g_cnt[NN];
__device__ int   g_off[NN];
__device__ int   g_rank[EE];
__device__ int   g_esrc[EE];
__device__ int   g_bsum[SCAN_B];
__device__ int   g_boff[SCAN_B];

__device__ __forceinline__ float to_tf32(float x) {
    float r;
    asm("cvt.rna.tf32.f32 %0, %1;" : "=f"(r) : "f"(x));
    return r;
}

// ---------------- CSR build (rank-based: atomic only in hist) ----------------
__global__ void k_hist(const int* __restrict__ ei, int E) {
    int i = blockIdx.x * blockDim.x + threadIdx.x;
    if (i < E) {
        int d = ei[E + i];
        g_rank[i] = atomicAdd(g_cnt + d, 1);   // rank within dst bucket
    }
}

__global__ __launch_bounds__(256) void k_scan1() {
    __shared__ int sh[256];
    int t = threadIdx.x;
    int i = blockIdx.x * 256 + t;
    int v = (i < NN) ? g_cnt[i] : 0;
    sh[t] = v;
    __syncthreads();
#pragma unroll
    for (int o = 128; o > 0; o >>= 1) {
        if (t < o) sh[t] += sh[t + o];
        __syncthreads();
    }
    if (t == 0) g_bsum[blockIdx.x] = sh[0];
}

__global__ __launch_bounds__(256) void k_scan2() {
    __shared__ int sh[256];
    int t = threadIdx.x;
    int v = (t < SCAN_B) ? g_bsum[t] : 0;
    sh[t] = v;
    __syncthreads();
#pragma unroll
    for (int o = 1; o < 256; o <<= 1) {
        int u = (t >= o) ? sh[t - o] : 0;
        __syncthreads();
        sh[t] += u;
        __syncthreads();
    }
    if (t < SCAN_B) g_boff[t] = sh[t] - v;
}

__global__ __launch_bounds__(256) void k_scan3() {
    __shared__ int sh[256];
    int t = threadIdx.x;
    int i = blockIdx.x * 256 + t;
    int v = (i < NN) ? g_cnt[i] : 0;
    sh[t] = v;
    __syncthreads();
#pragma unroll
    for (int o = 1; o < 256; o <<= 1) {
        int u = (t >= o) ? sh[t - o] : 0;
        __syncthreads();
        sh[t] += u;
        __syncthreads();
    }
    if (i < NN) g_off[i] = g_boff[blockIdx.x] + sh[t] - v;
}

// no atomics: position = off[d] + precomputed rank
__global__ void k_scatter(const int* __restrict__ ei, int E) {
    int i = blockIdx.x * blockDim.x + threadIdx.x;
    if (i >= E) return;
    int s = ei[i];
    int d = ei[E + i];
    int r = g_rank[i];
    g_esrc[g_off[d] + r] = s;
}

// ---------------- FUSED GEMM: h = lrelu(X@Wd^T+bd); g = h@Wg^T; logits ------
#define G1_BM 128
#define G1_BK 32
#define G1_ROW 36
#define G1_TILE (G1_BM * G1_ROW)          // 4608 floats
#define PIPE_FLOATS (4 * G1_TILE)         // 18432 floats (2 stages A+B)
#define HS_ROW 132                        // h tile row stride (128 + 4 pad)
#define WGS_OFF PIPE_FLOATS               // Wgs: [64][HS_ROW]
#define PS_OFF  (WGS_OFF + OD * HS_ROW)   // ps_sh[128][2]
#define PD_OFF  (PS_OFF + 256)
#define ATS_OFF (PD_OFF + 256)
#define ATD_OFF (ATS_OFF + OD)
#define FG_SMEM ((ATD_OFF + OD) * 4)      // total bytes

__global__ __launch_bounds__(256) void k_fused_gemm(const float* __restrict__ X,
                                                    const float* __restrict__ Wd,
                                                    const float* __restrict__ bd,
                                                    const float* __restrict__ Wg,
                                                    const float* __restrict__ att_s,
                                                    const float* __restrict__ att_d) {
    extern __shared__ float smem[];
    float* As  = smem;                  // [2][128][36]
    float* Bs  = smem + 2 * G1_TILE;    // [2][128][36]
    float* hs  = smem;                  // overlay after phase 1: [128][HS_ROW]
    float* Wgs = smem + WGS_OFF;        // [64][HS_ROW]
    float* ps_sh = smem + PS_OFF;       // [128][2]
    float* pd_sh = smem + PD_OFF;
    float* ats = smem + ATS_OFF;
    float* atd = smem + ATD_OFF;

    const int tid  = threadIdx.x;
    const int warp = tid >> 5;
    const int lane = tid & 31;
    const int g    = lane >> 2;
    const int tig  = lane & 3;
    const int wm   = warp >> 2;
    const int wn   = warp & 3;
    const int row0 = blockIdx.x * G1_BM;

    const uint32_t a_base = (uint32_t)__cvta_generic_to_shared(As);
    const uint32_t b_base = (uint32_t)__cvta_generic_to_shared(Bs);

#pragma unroll
    for (int i = 0; i < 8; i++) {
        int f = tid + i * 256;
        int c = f >> 5;
        int kq = f & 31;
        float4 v = *reinterpret_cast<const float4*>(Wg + (size_t)c * EM + kq * 4);
        v.x = to_tf32(v.x); v.y = to_tf32(v.y);
        v.z = to_tf32(v.z); v.w = to_tf32(v.w);
        *reinterpret_cast<float4*>(&Wgs[c * HS_ROW + kq * 4]) = v;
    }
    if (tid < OD) { ats[tid] = att_s[tid]; atd[tid] = att_d[tid]; }

    float acc[4][4][4];
#pragma unroll
    for (int i = 0; i < 4; i++)
#pragma unroll
        for (int j = 0; j < 4; j++)
#pragma unroll
            for (int r = 0; r < 4; r++) acc[i][j][r] = 0.f;

    auto load_stage = [&](int st, int k0) {
#pragma unroll
        for (int i = 0; i < 4; i++) {
            int f  = tid + i * 256;
            int r  = f >> 3;
            int kq = f & 7;
            int rg = row0 + r;
            if (rg > NN - 1) rg = NN - 1;
            const float* src = X + (size_t)rg * KD + k0 + kq * 4;
            uint32_t dst = a_base + (uint32_t)((st * G1_TILE + r * G1_ROW + kq * 4) * 4);
            asm volatile("cp.async.cg.shared.global [%0], [%1], 16;"
                         :: "r"(dst), "l"(src));
        }
#pragma unroll
        for (int i = 0; i < 4; i++) {
            int f  = tid + i * 256;
            int c  = f >> 3;
            int kq = f & 7;
            const float* src = Wd + (size_t)c * KD + k0 + kq * 4;
            uint32_t dst = b_base + (uint32_t)((st * G1_TILE + c * G1_ROW + kq * 4) * 4);
            asm volatile("cp.async.cg.shared.global [%0], [%1], 16;"
                         :: "r"(dst), "l"(src));
        }
        asm volatile("cp.async.commit_group;");
    };

    const int NCH = KD / G1_BK;   // 16
    load_stage(0, 0);
    for (int kt = 0; kt < NCH; kt++) {
        int st = kt & 1;
        if (kt + 1 < NCH) {
            load_stage(st ^ 1, (kt + 1) * G1_BK);
            asm volatile("cp.async.wait_group 1;");
        } else {
            asm volatile("cp.async.wait_group 0;");
        }
        __syncthreads();

        const float* A0 = As + st * G1_TILE;
        const float* B0 = Bs + st * G1_TILE;
#pragma unroll
        for (int ks = 0; ks < 4; ks++) {
            const int kb = ks * 8;
            uint32_t af[4][4];
#pragma unroll
            for (int mt = 0; mt < 4; mt++) {
                int ra = wm * 64 + mt * 16 + g;
                af[mt][0] = __float_as_uint(to_tf32(A0[ra * G1_ROW + kb + tig]));
                af[mt][1] = __float_as_uint(to_tf32(A0[(ra + 8) * G1_ROW + kb + tig]));
                af[mt][2] = __float_as_uint(to_tf32(A0[ra * G1_ROW + kb + tig + 4]));
                af[mt][3] = __float_as_uint(to_tf32(A0[(ra + 8) * G1_ROW + kb + tig + 4]));
            }
            uint32_t bf[4][2];
#pragma unroll
            for (int nt = 0; nt < 4; nt++) {
                int nb = wn * 32 + nt * 8 + g;
                bf[nt][0] = __float_as_uint(to_tf32(B0[nb * G1_ROW + kb + tig]));
                bf[nt][1] = __float_as_uint(to_tf32(B0[nb * G1_ROW + kb + tig + 4]));
            }
#pragma unroll
            for (int mt = 0; mt < 4; mt++)
#pragma unroll
                for (int nt = 0; nt < 4; nt++) {
                    asm volatile(
                        "mma.sync.aligned.m16n8k8.row.col.f32.tf32.tf32.f32 "
                        "{%0,%1,%2,%3}, {%4,%5,%6,%7}, {%8,%9}, {%0,%1,%2,%3};"
                        : "+f"(acc[mt][nt][0]), "+f"(acc[mt][nt][1]),
                          "+f"(acc[mt][nt][2]), "+f"(acc[mt][nt][3])
                        : "r"(af[mt][0]), "r"(af[mt][1]), "r"(af[mt][2]), "r"(af[mt][3]),
                          "r"(bf[nt][0]), "r"(bf[nt][1]));
                }
        }
        __syncthreads();
    }

    // phase-1 epilogue: bias + lrelu + tf32-round, h tile -> smem (overlay)
#pragma unroll
    for (int mt = 0; mt < 4; mt++) {
#pragma unroll
        for (int half = 0; half < 2; half++) {
            int rloc = wm * 64 + mt * 16 + g + half * 8;
#pragma unroll
            for (int nt = 0; nt < 4; nt++) {
                int c = wn * 32 + nt * 8 + tig * 2;
                float v0 = acc[mt][nt][half * 2]     + __ldg(bd + c);
                float v1 = acc[mt][nt][half * 2 + 1] + __ldg(bd + c + 1);
                v0 = v0 > 0.f ? v0 : 0.01f * v0;
                v1 = v1 > 0.f ? v1 : 0.01f * v1;
                *reinterpret_cast<float2*>(&hs[rloc * HS_ROW + c]) =
                    make_float2(to_tf32(v0), to_tf32(v1));
            }
        }
    }
    __syncthreads();

    // ---- phase 2: g = h @ Wg^T (128x64, K=128), all operands in smem ----
    const int wm2 = warp >> 1;
    const int wn2 = warp & 1;

    float acc2[2][4][4];
#pragma unroll
    for (int i = 0; i < 2; i++)
#pragma unroll
        for (int j = 0; j < 4; j++)
#pragma unroll
            for (int r = 0; r < 4; r++) acc2[i][j][r] = 0.f;

#pragma unroll
    for (int ks = 0; ks < 16; ks++) {
        const int kb = ks * 8;
        uint32_t af[2][4];
#pragma unroll
        for (int mt = 0; mt < 2; mt++) {
            int ra = wm2 * 32 + mt * 16 + g;
            af[mt][0] = __float_as_uint(hs[ra * HS_ROW + kb + tig]);
            af[mt][1] = __float_as_uint(hs[(ra + 8) * HS_ROW + kb + tig]);
            af[mt][2] = __float_as_uint(hs[ra * HS_ROW + kb + tig + 4]);
            af[mt][3] = __float_as_uint(hs[(ra + 8) * HS_ROW + kb + tig + 4]);
        }
        uint32_t bf[4][2];
#pragma unroll
        for (int nt = 0; nt < 4; nt++) {
            int nb = wn2 * 32 + nt * 8 + g;
            bf[nt][0] = __float_as_uint(Wgs[nb * HS_ROW + kb + tig]);
            bf[nt][1] = __float_as_uint(Wgs[nb * HS_ROW + kb + tig + 4]);
        }
#pragma unroll
        for (int mt = 0; mt < 2; mt++)
#pragma unroll
            for (int nt = 0; nt < 4; nt++) {
                asm volatile(
                    "mma.sync.aligned.m16n8k8.row.col.f32.tf32.tf32.f32 "
                    "{%0,%1,%2,%3}, {%4,%5,%6,%7}, {%8,%9}, {%0,%1,%2,%3};"
                    : "+f"(acc2[mt][nt][0]), "+f"(acc2[mt][nt][1]),
                      "+f"(acc2[mt][nt][2]), "+f"(acc2[mt][nt][3])
                    : "r"(af[mt][0]), "r"(af[mt][1]), "r"(af[mt][2]), "r"(af[mt][3]),
                      "r"(bf[nt][0]), "r"(bf[nt][1]));
            }
    }

#pragma unroll
    for (int mt = 0; mt < 2; mt++) {
#pragma unroll
        for (int half = 0; half < 2; half++) {
            int rloc = wm2 * 32 + mt * 16 + g + half * 8;
            int r = row0 + rloc;
            float ps = 0.f, pd = 0.f;
#pragma unroll
            for (int nt = 0; nt < 4; nt++) {
                int c = wn2 * 32 + nt * 8 + tig * 2;
                float v0 = acc2[mt][nt][half * 2];
                float v1 = acc2[mt][nt][half * 2 + 1];
                if (r < NN)
                    *reinterpret_cast<float2*>(g_g + (size_t)r * OD + c) = make_float2(v0, v1);
                ps = fmaf(v0, ats[c], fmaf(v1, ats[c + 1], ps));
                pd = fmaf(v0, atd[c], fmaf(v1, atd[c + 1], pd));
            }
            ps += __shfl_xor_sync(0xffffffffu, ps, 1);
            ps += __shfl_xor_sync(0xffffffffu, ps, 2);
            pd += __shfl_xor_sync(0xffffffffu, pd, 1);
            pd += __shfl_xor_sync(0xffffffffu, pd, 2);
            if (tig == 0) { ps_sh[rloc * 2 + wn2] = ps; pd_sh[rloc * 2 + wn2] = pd; }
        }
    }
    __syncthreads();
    if (tid < G1_BM) {
        int r = row0 + tid;
        if (r < NN) {
            g_as[r] = ps_sh[tid * 2] + ps_sh[tid * 2 + 1];
            g_ad[r] = pd_sh[tid * 2] + pd_sh[tid * 2 + 1];
        }
    }
}

// ---------------- fused softmax + gather accumulate ----------------
// 1 warp per dst. Half-warp float4 gathers: each half-warp serves one edge with
// 16 lanes x float4 (256B row) -> 16 LDG.128 + 32 SHFL per 32-edge batch
// (vs 32 LDG.64 + 64 SHFL). Weight chain pipelined across batches.
__global__ __launch_bounds__(256) void k_accum(float* __restrict__ out,
                                               const float* __restrict__ bg) {
    const unsigned FULL = 0xffffffffu;
    int w    = (blockIdx.x * blockDim.x + threadIdx.x) >> 5;
    int lane = threadIdx.x & 31;
    if (w >= NN) return;
    int half = lane >> 4;          // 0/1
    int col4 = (lane & 15) * 4;    // float4 column base
    int beg = g_off[w];
    int end = beg + g_cnt[w];
    float a_d = g_ad[w];

    // self loop (half 0 only, to avoid double count after cross-half reduce)
    float e0 = g_as[w] + a_d;
    e0 = e0 > 0.f ? e0 : 0.2f * e0;
    float wt_self = __expf(e0);
    float4 acc = make_float4(0.f, 0.f, 0.f, 0.f);
    if (half == 0) {
        float4 gw = *reinterpret_cast<const float4*>(g_g + (size_t)w * OD + col4);
        acc.x = wt_self * gw.x; acc.y = wt_self * gw.y;
        acc.z = wt_self * gw.z; acc.w = wt_self * gw.w;
    }
    float den_l = (lane == 0) ? wt_self : 0.f;

    // prologue: weight chain for first batch (one edge per lane)
    int   s_l  = w;
    float wt_l = 0.f;
    if (beg < end && beg + lane < end) {
        s_l = g_esrc[beg + lane];
        float e = g_as[s_l] + a_d;
        e = e > 0.f ? e : 0.2f * e;
        wt_l = __expf(e);
    }

    for (int j = beg; j < end; j += 32) {
        // prefetch next batch's chain
        int   jn   = j + 32;
        int   s_nl = w;
        float a_nl = 0.f;
        bool  nv   = false;
        if (jn < end && jn + lane < end) {
            s_nl = g_esrc[jn + lane];
            a_nl = g_as[s_nl];
            nv   = true;
        }

        den_l += wt_l;
        // this half-warp processes edges [half*16, half*16+16) of the batch
#pragma unroll
        for (int g8 = 0; g8 < 2; g8++) {
            float4 gvs[8];
#pragma unroll
            for (int u = 0; u < 8; u++) {
                int eidx = half * 16 + g8 * 8 + u;
                int s = __shfl_sync(FULL, s_l, eidx);
                gvs[u] = *reinterpret_cast<const float4*>(g_g + (size_t)s * OD + col4);
            }
#pragma unroll
            for (int u = 0; u < 8; u++) {
                float wt = __shfl_sync(FULL, wt_l, half * 16 + g8 * 8 + u);
                acc.x = fmaf(wt, gvs[u].x, acc.x);
                acc.y = fmaf(wt, gvs[u].y, acc.y);
                acc.z = fmaf(wt, gvs[u].z, acc.z);
                acc.w = fmaf(wt, gvs[u].w, acc.w);
            }
        }

        float e = a_nl + a_d;
        e = e > 0.f ? e : 0.2f * e;
        wt_l = nv ? __expf(e) : 0.f;
        s_l  = s_nl;
    }
    // reduce den across all lanes
#pragma unroll
    for (int o = 16; o > 0; o >>= 1)
        den_l += __shfl_xor_sync(FULL, den_l, o);
    // cross-half accumulator reduction (lanes u and u+16 hold same cols)
    acc.x += __shfl_xor_sync(FULL, acc.x, 16);
    acc.y += __shfl_xor_sync(FULL, acc.y, 16);
    acc.z += __shfl_xor_sync(FULL, acc.z, 16);
    acc.w += __shfl_xor_sync(FULL, acc.w, 16);

    if (half == 0) {
        float inv = 1.f / den_l;
        float4 b4 = *reinterpret_cast<const float4*>(bg + col4);
        float4 o4 = make_float4(acc.x * inv + b4.x, acc.y * inv + b4.y,
                                acc.z * inv + b4.z, acc.w * inv + b4.w);
        *reinterpret_cast<float4*>(out + (size_t)w * OD + col4) = o4;
    }
}

// ---------------- launch ----------------
extern "C" void kernel_launch(void* const* d_in, const int* in_sizes, int n_in,
                              void* d_out, int out_size) {
    const float* x   = (const float*)d_in[0];
    const int*   ei  = (const int*)  d_in[1];
    const float* Wd  = (const float*)d_in[2];
    const float* bd  = (const float*)d_in[3];
    const float* Wg  = (const float*)d_in[4];
    const float* ats = (const float*)d_in[5];
    const float* atd = (const float*)d_in[6];
    const float* bg  = (const float*)d_in[7];
    float* out = (float*)d_out;

    const int E = in_sizes[1] / 2;

    static cudaStream_t s2 = nullptr;
    static cudaEvent_t ev_fork = nullptr, ev_join = nullptr;
    static void* cnt_ptr = nullptr;
    if (!s2) {
        cudaStreamCreate(&s2);
        cudaEventCreateWithFlags(&ev_fork, cudaEventDisableTiming);
        cudaEventCreateWithFlags(&ev_join, cudaEventDisableTiming);
        cudaGetSymbolAddress(&cnt_ptr, g_cnt);
        cudaFuncSetAttribute(k_fused_gemm, cudaFuncAttributeMaxDynamicSharedMemorySize, FG_SMEM);
    }

    // fork: CSR build on s2
    cudaEventRecord(ev_fork, 0);
    cudaStreamWaitEvent(s2, ev_fork, 0);

    cudaMemsetAsync(cnt_ptr, 0, NN * sizeof(int), s2);
    k_hist<<<(E + 255) / 256, 256, 0, s2>>>(ei, E);
    k_scan1<<<SCAN_B, 256, 0, s2>>>();
    k_scan2<<<1, 256, 0, s2>>>();
    k_scan3<<<SCAN_B, 256, 0, s2>>>();

    k_fused_gemm<<<(NN + G1_BM - 1) / G1_BM, 256, FG_SMEM>>>(x, Wd, bd, Wg, ats, atd);

    k_scatter<<<(E + 255) / 256, 256, 0, s2>>>(ei, E);
    cudaEventRecord(ev_join, s2);

    cudaStreamWaitEvent(0, ev_join, 0);
    k_accum<<<(NN * 32 + 255) / 256, 256>>>(out, bg);
}

// round 16
// speedup vs baseline: 1.0695x; 1.0250x over previous
#include <cuda_runtime.h>
#include <cstdint>

#define NN 50000
#define KD 512
#define EM 128
#define OD 64
#define EE 1600000
#define SCAN_B 196            // 196 * 256 = 50176 >= NN

// ---------------- scratch (device globals) ----------------
__device__ float g_g[(size_t)NN * OD];
__device__ float g_as[NN];
__device__ float g_ad[NN];
__device__ int   g_cnt[NN];
__device__ int   g_off[NN];
__device__ int   g_rank[EE];
__device__ int   g_esrc[EE];
__device__ int   g_bsum[SCAN_B];
__device__ int   g_boff[SCAN_B];

__device__ __forceinline__ float to_tf32(float x) {
    float r;
    asm("cvt.rna.tf32.f32 %0, %1;" : "=f"(r) : "f"(x));
    return r;
}

// ---------------- CSR build (rank-based: atomic only in hist) ----------------
__global__ void k_hist(const int* __restrict__ ei, int E) {
    int i = blockIdx.x * blockDim.x + threadIdx.x;
    if (i < E) {
        int d = ei[E + i];
        g_rank[i] = atomicAdd(g_cnt + d, 1);   // rank within dst bucket
    }
}

__global__ __launch_bounds__(256) void k_scan1() {
    __shared__ int sh[256];
    int t = threadIdx.x;
    int i = blockIdx.x * 256 + t;
    int v = (i < NN) ? g_cnt[i] : 0;
    sh[t] = v;
    __syncthreads();
#pragma unroll
    for (int o = 128; o > 0; o >>= 1) {
        if (t < o) sh[t] += sh[t + o];
        __syncthreads();
    }
    if (t == 0) g_bsum[blockIdx.x] = sh[0];
}

__global__ __launch_bounds__(256) void k_scan2() {
    __shared__ int sh[256];
    int t = threadIdx.x;
    int v = (t < SCAN_B) ? g_bsum[t] : 0;
    sh[t] = v;
    __syncthreads();
#pragma unroll
    for (int o = 1; o < 256; o <<= 1) {
        int u = (t >= o) ? sh[t - o] : 0;
        __syncthreads();
        sh[t] += u;
        __syncthreads();
    }
    if (t < SCAN_B) g_boff[t] = sh[t] - v;
}

__global__ __launch_bounds__(256) void k_scan3() {
    __shared__ int sh[256];
    int t = threadIdx.x;
    int i = blockIdx.x * 256 + t;
    int v = (i < NN) ? g_cnt[i] : 0;
    sh[t] = v;
    __syncthreads();
#pragma unroll
    for (int o = 1; o < 256; o <<= 1) {
        int u = (t >= o) ? sh[t - o] : 0;
        __syncthreads();
        sh[t] += u;
        __syncthreads();
    }
    if (i < NN) g_off[i] = g_boff[blockIdx.x] + sh[t] - v;
}

// no atomics: position = off[d] + precomputed rank
__global__ void k_scatter(const int* __restrict__ ei, int E) {
    int i = blockIdx.x * blockDim.x + threadIdx.x;
    if (i >= E) return;
    int s = ei[i];
    int d = ei[E + i];
    int r = g_rank[i];
    g_esrc[g_off[d] + r] = s;
}

// ---------------- FUSED GEMM: h = lrelu(X@Wd^T+bd); g = h@Wg^T; logits ------
#define G1_BM 128
#define G1_BK 32
#define G1_ROW 36
#define G1_TILE (G1_BM * G1_ROW)          // 4608 floats
#define PIPE_FLOATS (4 * G1_TILE)         // 18432 floats (2 stages A+B)
#define HS_ROW 132                        // h tile row stride (128 + 4 pad)
#define WGS_OFF PIPE_FLOATS               // Wgs: [64][HS_ROW]
#define PS_OFF  (WGS_OFF + OD * HS_ROW)   // ps_sh[128][2]
#define PD_OFF  (PS_OFF + 256)
#define ATS_OFF (PD_OFF + 256)
#define ATD_OFF (ATS_OFF + OD)
#define FG_SMEM ((ATD_OFF + OD) * 4)      // total bytes

__global__ __launch_bounds__(256) void k_fused_gemm(const float* __restrict__ X,
                                                    const float* __restrict__ Wd,
                                                    const float* __restrict__ bd,
                                                    const float* __restrict__ Wg,
                                                    const float* __restrict__ att_s,
                                                    const float* __restrict__ att_d) {
    extern __shared__ float smem[];
    float* As  = smem;                  // [2][128][36]
    float* Bs  = smem + 2 * G1_TILE;    // [2][128][36]
    float* hs  = smem;                  // overlay after phase 1: [128][HS_ROW]
    float* Wgs = smem + WGS_OFF;        // [64][HS_ROW]
    float* ps_sh = smem + PS_OFF;       // [128][2]
    float* pd_sh = smem + PD_OFF;
    float* ats = smem + ATS_OFF;
    float* atd = smem + ATD_OFF;

    const int tid  = threadIdx.x;
    const int warp = tid >> 5;
    const int lane = tid & 31;
    const int g    = lane >> 2;
    const int tig  = lane & 3;
    const int wm   = warp >> 2;
    const int wn   = warp & 3;
    const int row0 = blockIdx.x * G1_BM;

    const uint32_t a_base = (uint32_t)__cvta_generic_to_shared(As);
    const uint32_t b_base = (uint32_t)__cvta_generic_to_shared(Bs);

#pragma unroll
    for (int i = 0; i < 8; i++) {
        int f = tid + i * 256;
        int c = f >> 5;
        int kq = f & 31;
        float4 v = *reinterpret_cast<const float4*>(Wg + (size_t)c * EM + kq * 4);
        v.x = to_tf32(v.x); v.y = to_tf32(v.y);
        v.z = to_tf32(v.z); v.w = to_tf32(v.w);
        *reinterpret_cast<float4*>(&Wgs[c * HS_ROW + kq * 4]) = v;
    }
    if (tid < OD) { ats[tid] = att_s[tid]; atd[tid] = att_d[tid]; }

    float acc[4][4][4];
#pragma unroll
    for (int i = 0; i < 4; i++)
#pragma unroll
        for (int j = 0; j < 4; j++)
#pragma unroll
            for (int r = 0; r < 4; r++) acc[i][j][r] = 0.f;

    auto load_stage = [&](int st, int k0) {
#pragma unroll
        for (int i = 0; i < 4; i++) {
            int f  = tid + i * 256;
            int r  = f >> 3;
            int kq = f & 7;
            int rg = row0 + r;
            if (rg > NN - 1) rg = NN - 1;
            const float* src = X + (size_t)rg * KD + k0 + kq * 4;
            uint32_t dst = a_base + (uint32_t)((st * G1_TILE + r * G1_ROW + kq * 4) * 4);
            asm volatile("cp.async.cg.shared.global [%0], [%1], 16;"
                         :: "r"(dst), "l"(src));
        }
#pragma unroll
        for (int i = 0; i < 4; i++) {
            int f  = tid + i * 256;
            int c  = f >> 3;
            int kq = f & 7;
            const float* src = Wd + (size_t)c * KD + k0 + kq * 4;
            uint32_t dst = b_base + (uint32_t)((st * G1_TILE + c * G1_ROW + kq * 4) * 4);
            asm volatile("cp.async.cg.shared.global [%0], [%1], 16;"
                         :: "r"(dst), "l"(src));
        }
        asm volatile("cp.async.commit_group;");
    };

    const int NCH = KD / G1_BK;   // 16
    load_stage(0, 0);
    for (int kt = 0; kt < NCH; kt++) {
        int st = kt & 1;
        if (kt + 1 < NCH) {
            load_stage(st ^ 1, (kt + 1) * G1_BK);
            asm volatile("cp.async.wait_group 1;");
        } else {
            asm volatile("cp.async.wait_group 0;");
        }
        __syncthreads();

        const float* A0 = As + st * G1_TILE;
        const float* B0 = Bs + st * G1_TILE;
#pragma unroll
        for (int ks = 0; ks < 4; ks++) {
            const int kb = ks * 8;
            uint32_t af[4][4];
#pragma unroll
            for (int mt = 0; mt < 4; mt++) {
                int ra = wm * 64 + mt * 16 + g;
                af[mt][0] = __float_as_uint(to_tf32(A0[ra * G1_ROW + kb + tig]));
                af[mt][1] = __float_as_uint(to_tf32(A0[(ra + 8) * G1_ROW + kb + tig]));
                af[mt][2] = __float_as_uint(to_tf32(A0[ra * G1_ROW + kb + tig + 4]));
                af[mt][3] = __float_as_uint(to_tf32(A0[(ra + 8) * G1_ROW + kb + tig + 4]));
            }
            uint32_t bf[4][2];
#pragma unroll
            for (int nt = 0; nt < 4; nt++) {
                int nb = wn * 32 + nt * 8 + g;
                bf[nt][0] = __float_as_uint(to_tf32(B0[nb * G1_ROW + kb + tig]));
                bf[nt][1] = __float_as_uint(to_tf32(B0[nb * G1_ROW + kb + tig + 4]));
            }
#pragma unroll
            for (int mt = 0; mt < 4; mt++)
#pragma unroll
                for (int nt = 0; nt < 4; nt++) {
                    asm volatile(
                        "mma.sync.aligned.m16n8k8.row.col.f32.tf32.tf32.f32 "
                        "{%0,%1,%2,%3}, {%4,%5,%6,%7}, {%8,%9}, {%0,%1,%2,%3};"
                        : "+f"(acc[mt][nt][0]), "+f"(acc[mt][nt][1]),
                          "+f"(acc[mt][nt][2]), "+f"(acc[mt][nt][3])
                        : "r"(af[mt][0]), "r"(af[mt][1]), "r"(af[mt][2]), "r"(af[mt][3]),
                          "r"(bf[nt][0]), "r"(bf[nt][1]));
                }
        }
        __syncthreads();
    }

    // phase-1 epilogue: bias + lrelu + tf32-round, h tile -> smem (overlay)
#pragma unroll
    for (int mt = 0; mt < 4; mt++) {
#pragma unroll
        for (int half = 0; half < 2; half++) {
            int rloc = wm * 64 + mt * 16 + g + half * 8;
#pragma unroll
            for (int nt = 0; nt < 4; nt++) {
                int c = wn * 32 + nt * 8 + tig * 2;
                float v0 = acc[mt][nt][half * 2]     + __ldg(bd + c);
                float v1 = acc[mt][nt][half * 2 + 1] + __ldg(bd + c + 1);
                v0 = v0 > 0.f ? v0 : 0.01f * v0;
                v1 = v1 > 0.f ? v1 : 0.01f * v1;
                *reinterpret_cast<float2*>(&hs[rloc * HS_ROW + c]) =
                    make_float2(to_tf32(v0), to_tf32(v1));
            }
        }
    }
    __syncthreads();

    // ---- phase 2: g = h @ Wg^T (128x64, K=128), all operands in smem ----
    const int wm2 = warp >> 1;
    const int wn2 = warp & 1;

    float acc2[2][4][4];
#pragma unroll
    for (int i = 0; i < 2; i++)
#pragma unroll
        for (int j = 0; j < 4; j++)
#pragma unroll
            for (int r = 0; r < 4; r++) acc2[i][j][r] = 0.f;

#pragma unroll
    for (int ks = 0; ks < 16; ks++) {
        const int kb = ks * 8;
        uint32_t af[2][4];
#pragma unroll
        for (int mt = 0; mt < 2; mt++) {
            int ra = wm2 * 32 + mt * 16 + g;
            af[mt][0] = __float_as_uint(hs[ra * HS_ROW + kb + tig]);
            af[mt][1] = __float_as_uint(hs[(ra + 8) * HS_ROW + kb + tig]);
            af[mt][2] = __float_as_uint(hs[ra * HS_ROW + kb + tig + 4]);
            af[mt][3] = __float_as_uint(hs[(ra + 8) * HS_ROW + kb + tig + 4]);
        }
        uint32_t bf[4][2];
#pragma unroll
        for (int nt = 0; nt < 4; nt++) {
            int nb = wn2 * 32 + nt * 8 + g;
            bf[nt][0] = __float_as_uint(Wgs[nb * HS_ROW + kb + tig]);
            bf[nt][1] = __float_as_uint(Wgs[nb * HS_ROW + kb + tig + 4]);
        }
#pragma unroll
        for (int mt = 0; mt < 2; mt++)
#pragma unroll
            for (int nt = 0; nt < 4; nt++) {
                asm volatile(
                    "mma.sync.aligned.m16n8k8.row.col.f32.tf32.tf32.f32 "
                    "{%0,%1,%2,%3}, {%4,%5,%6,%7}, {%8,%9}, {%0,%1,%2,%3};"
                    : "+f"(acc2[mt][nt][0]), "+f"(acc2[mt][nt][1]),
                      "+f"(acc2[mt][nt][2]), "+f"(acc2[mt][nt][3])
                    : "r"(af[mt][0]), "r"(af[mt][1]), "r"(af[mt][2]), "r"(af[mt][3]),
                      "r"(bf[nt][0]), "r"(bf[nt][1]));
            }
    }

#pragma unroll
    for (int mt = 0; mt < 2; mt++) {
#pragma unroll
        for (int half = 0; half < 2; half++) {
            int rloc = wm2 * 32 + mt * 16 + g + half * 8;
            int r = row0 + rloc;
            float ps = 0.f, pd = 0.f;
#pragma unroll
            for (int nt = 0; nt < 4; nt++) {
                int c = wn2 * 32 + nt * 8 + tig * 2;
                float v0 = acc2[mt][nt][half * 2];
                float v1 = acc2[mt][nt][half * 2 + 1];
                if (r < NN)
                    *reinterpret_cast<float2*>(g_g + (size_t)r * OD + c) = make_float2(v0, v1);
                ps = fmaf(v0, ats[c], fmaf(v1, ats[c + 1], ps));
                pd = fmaf(v0, atd[c], fmaf(v1, atd[c + 1], pd));
            }
            ps += __shfl_xor_sync(0xffffffffu, ps, 1);
            ps += __shfl_xor_sync(0xffffffffu, ps, 2);
            pd += __shfl_xor_sync(0xffffffffu, pd, 1);
            pd += __shfl_xor_sync(0xffffffffu, pd, 2);
            if (tig == 0) { ps_sh[rloc * 2 + wn2] = ps; pd_sh[rloc * 2 + wn2] = pd; }
        }
    }
    __syncthreads();
    if (tid < G1_BM) {
        int r = row0 + tid;
        if (r < NN) {
            g_as[r] = ps_sh[tid * 2] + ps_sh[tid * 2 + 1];
            g_ad[r] = pd_sh[tid * 2] + pd_sh[tid * 2 + 1];
        }
    }
}

// ---------------- fused softmax + gather accumulate ----------------
// 1 warp per dst, half-warp float4 gathers, pipelined weight chain.
// Degree-aware inner loop: only ceil(m/16) 16-edge groups are processed per
// batch (pad slots contributed exactly 0 before, so results are bit-identical,
// but ~17% of gather issue/FMA work is skipped for Poisson(32) degrees).
__global__ __launch_bounds__(256) void k_accum(float* __restrict__ out,
                                               const float* __restrict__ bg) {
    const unsigned FULL = 0xffffffffu;
    int w    = (blockIdx.x * blockDim.x + threadIdx.x) >> 5;
    int lane = threadIdx.x & 31;
    if (w >= NN) return;
    int half = lane >> 4;          // 0/1
    int col4 = (lane & 15) * 4;    // float4 column base
    int beg = g_off[w];
    int end = beg + g_cnt[w];
    float a_d = g_ad[w];

    // self loop (half 0 only, to avoid double count after cross-half reduce)
    float e0 = g_as[w] + a_d;
    e0 = e0 > 0.f ? e0 : 0.2f * e0;
    float wt_self = __expf(e0);
    float4 acc = make_float4(0.f, 0.f, 0.f, 0.f);
    if (half == 0) {
        float4 gw = *reinterpret_cast<const float4*>(g_g + (size_t)w * OD + col4);
        acc.x = wt_self * gw.x; acc.y = wt_self * gw.y;
        acc.z = wt_self * gw.z; acc.w = wt_self * gw.w;
    }
    float den_l = (lane == 0) ? wt_self : 0.f;

    // prologue: weight chain for first batch (one edge per lane)
    int   s_l  = w;
    float wt_l = 0.f;
    if (beg < end && beg + lane < end) {
        s_l = g_esrc[beg + lane];
        float e = g_as[s_l] + a_d;
        e = e > 0.f ? e : 0.2f * e;
        wt_l = __expf(e);
    }

    for (int j = beg; j < end; j += 32) {
        int m = end - j;
        if (m > 32) m = 32;
        // prefetch next batch's chain
        int   jn   = j + 32;
        int   s_nl = w;
        float a_nl = 0.f;
        bool  nv   = false;
        if (jn < end && jn + lane < end) {
            s_nl = g_esrc[jn + lane];
            a_nl = g_as[s_nl];
            nv   = true;
        }

        den_l += wt_l;
        // iteration t covers edges [t*16, t*16+16): half h handles 8 of them.
        // trip count uniform across the warp -> shfl FULL stays converged.
        int ntg = (m + 15) >> 4;   // 1 or 2
        for (int t = 0; t < ntg; t++) {
            float4 gvs[8];
#pragma unroll
            for (int u = 0; u < 8; u++) {
                int eidx = t * 16 + half * 8 + u;
                int s = __shfl_sync(FULL, s_l, eidx);
                gvs[u] = *reinterpret_cast<const float4*>(g_g + (size_t)s * OD + col4);
            }
#pragma unroll
            for (int u = 0; u < 8; u++) {
                float wt = __shfl_sync(FULL, wt_l, t * 16 + half * 8 + u);
                acc.x = fmaf(wt, gvs[u].x, acc.x);
                acc.y = fmaf(wt, gvs[u].y, acc.y);
                acc.z = fmaf(wt, gvs[u].z, acc.z);
                acc.w = fmaf(wt, gvs[u].w, acc.w);
            }
        }

        float e = a_nl + a_d;
        e = e > 0.f ? e : 0.2f * e;
        wt_l = nv ? __expf(e) : 0.f;
        s_l  = s_nl;
    }
    // reduce den across all lanes
#pragma unroll
    for (int o = 16; o > 0; o >>= 1)
        den_l += __shfl_xor_sync(FULL, den_l, o);
    // cross-half accumulator reduction (lanes u and u+16 hold same cols)
    acc.x += __shfl_xor_sync(FULL, acc.x, 16);
    acc.y += __shfl_xor_sync(FULL, acc.y, 16);
    acc.z += __shfl_xor_sync(FULL, acc.z, 16);
    acc.w += __shfl_xor_sync(FULL, acc.w, 16);

    if (half == 0) {
        float inv = 1.f / den_l;
        float4 b4 = *reinterpret_cast<const float4*>(bg + col4);
        float4 o4 = make_float4(acc.x * inv + b4.x, acc.y * inv + b4.y,
                                acc.z * inv + b4.z, acc.w * inv + b4.w);
        *reinterpret_cast<float4*>(out + (size_t)w * OD + col4) = o4;
    }
}

// ---------------- launch ----------------
extern "C" void kernel_launch(void* const* d_in, const int* in_sizes, int n_in,
                              void* d_out, int out_size) {
    const float* x   = (const float*)d_in[0];
    const int*   ei  = (const int*)  d_in[1];
    const float* Wd  = (const float*)d_in[2];
    const float* bd  = (const float*)d_in[3];
    const float* Wg  = (const float*)d_in[4];
    const float* ats = (const float*)d_in[5];
    const float* atd = (const float*)d_in[6];
    const float* bg  = (const float*)d_in[7];
    float* out = (float*)d_out;

    const int E = in_sizes[1] / 2;

    static cudaStream_t s2 = nullptr;
    static cudaEvent_t ev_fork = nullptr, ev_join = nullptr;
    static void* cnt_ptr = nullptr;
    if (!s2) {
        cudaStreamCreate(&s2);
        cudaEventCreateWithFlags(&ev_fork, cudaEventDisableTiming);
        cudaEventCreateWithFlags(&ev_join, cudaEventDisableTiming);
        cudaGetSymbolAddress(&cnt_ptr, g_cnt);
        cudaFuncSetAttribute(k_fused_gemm, cudaFuncAttributeMaxDynamicSharedMemorySize, FG_SMEM);
    }

    // fork: CSR build on s2
    cudaEventRecord(ev_fork, 0);
    cudaStreamWaitEvent(s2, ev_fork, 0);

    cudaMemsetAsync(cnt_ptr, 0, NN * sizeof(int), s2);
    k_hist<<<(E + 255) / 256, 256, 0, s2>>>(ei, E);
    k_scan1<<<SCAN_B, 256, 0, s2>>>();
    k_scan2<<<1, 256, 0, s2>>>();
    k_scan3<<<SCAN_B, 256, 0, s2>>>();

    k_fused_gemm<<<(NN + G1_BM - 1) / G1_BM, 256, FG_SMEM>>>(x, Wd, bd, Wg, ats, atd);

    k_scatter<<<(E + 255) / 256, 256, 0, s2>>>(ei, E);
    cudaEventRecord(ev_join, s2);

    cudaStreamWaitEvent(0, ev_join, 0);
    k_accum<<<(NN * 32 + 255) / 256, 256>>>(out, bg);
}